// round 1
// baseline (speedup 1.0000x reference)
#include <cuda_runtime.h>
#include <cuda_bf16.h>

#define NUM_USERS 100000
#define NUM_ITEMS 50000
#define DIM 64
#define N_TOTAL (NUM_USERS + NUM_ITEMS)
#define NNZ 4800000
#define TOT (N_TOTAL * DIM)   // 9,600,000 floats = 38.4 MB per buffer

// Scratch (allocation-free): ping-pong layer buffers + running sum for the mean.
__device__ __align__(16) float g_bufA[TOT];
__device__ __align__(16) float g_bufB[TOT];
__device__ __align__(16) float g_acc[TOT];

// ---------------------------------------------------------------------------
// init: bufA = concat(user_emb, item_emb); acc = bufA; bufB = 0
// ---------------------------------------------------------------------------
__global__ void lg_init(const float* __restrict__ ue, const float* __restrict__ ie) {
    const int tot4 = TOT / 4;
    int i = blockIdx.x * blockDim.x + threadIdx.x;
    if (i >= tot4) return;
    const int user4 = (NUM_USERS * DIM) / 4;
    float4 v = (i < user4) ? __ldg((const float4*)ue + i)
                           : __ldg((const float4*)ie + (i - user4));
    ((float4*)g_bufA)[i] = v;
    ((float4*)g_acc)[i]  = v;
    ((float4*)g_bufB)[i] = make_float4(0.f, 0.f, 0.f, 0.f);
}

// ---------------------------------------------------------------------------
// spmm: y[row] += val * x[col], COO, 16 lanes per edge, one v4 red per lane.
// ---------------------------------------------------------------------------
__global__ void lg_spmm(const int* __restrict__ rows, const int* __restrict__ cols,
                        const float* __restrict__ vals,
                        const float* __restrict__ x, float* __restrict__ y) {
    int gid  = blockIdx.x * blockDim.x + threadIdx.x;
    int e    = gid >> 4;          // edge index
    int lane = gid & 15;          // which float4 of the 64-float row
    if (e >= NNZ) return;

    int   r = __ldg(rows + e);
    int   c = __ldg(cols + e);
    float v = __ldg(vals + e);

    float4 xv = __ldg((const float4*)(x + (size_t)c * DIM) + lane);
    float4 p  = make_float4(xv.x * v, xv.y * v, xv.z * v, xv.w * v);

    float* dst = y + (size_t)r * DIM + lane * 4;
    asm volatile("red.global.add.v4.f32 [%0], {%1, %2, %3, %4};"
                 :: "l"(dst), "f"(p.x), "f"(p.y), "f"(p.z), "f"(p.w)
                 : "memory");
}

// ---------------------------------------------------------------------------
// post: acc += y (layer result); zero the other buffer for the next layer.
// ---------------------------------------------------------------------------
__global__ void lg_post(const float* __restrict__ y, float* __restrict__ zero_me) {
    const int tot4 = TOT / 4;
    int i = blockIdx.x * blockDim.x + threadIdx.x;
    if (i >= tot4) return;
    float4 a = ((const float4*)g_acc)[i];
    float4 b = ((const float4*)y)[i];
    a.x += b.x; a.y += b.y; a.z += b.z; a.w += b.w;
    ((float4*)g_acc)[i] = a;
    ((float4*)zero_me)[i] = make_float4(0.f, 0.f, 0.f, 0.f);
}

// ---------------------------------------------------------------------------
// final: out = (acc + y_last) * 0.25   (mean over 4 embeddings)
// ---------------------------------------------------------------------------
__global__ void lg_final(const float* __restrict__ y, float* __restrict__ out) {
    const int tot4 = TOT / 4;
    int i = blockIdx.x * blockDim.x + threadIdx.x;
    if (i >= tot4) return;
    float4 a = ((const float4*)g_acc)[i];
    float4 b = ((const float4*)y)[i];
    float4 o = make_float4((a.x + b.x) * 0.25f, (a.y + b.y) * 0.25f,
                           (a.z + b.z) * 0.25f, (a.w + b.w) * 0.25f);
    ((float4*)out)[i] = o;
}

extern "C" void kernel_launch(void* const* d_in, const int* in_sizes, int n_in,
                              void* d_out, int out_size) {
    const float* ue   = (const float*)d_in[0];   // user_emb  [100000, 64] f32
    const float* ie   = (const float*)d_in[1];   // item_emb  [50000, 64]  f32
    const float* vals = (const float*)d_in[2];   // adj_vals  [4.8M] f32
    const int*   rows = (const int*)  d_in[3];   // adj_rows  [4.8M] i32
    const int*   cols = (const int*)  d_in[4];   // adj_cols  [4.8M] i32
    float* out = (float*)d_out;

    float *bufA, *bufB;
    cudaGetSymbolAddress((void**)&bufA, g_bufA);
    cudaGetSymbolAddress((void**)&bufB, g_bufB);

    const int TPB = 256;
    const int grid_elem = (TOT / 4 + TPB - 1) / TPB;           // 9375 blocks
    const int grid_spmm = ((size_t)NNZ * 16 + TPB - 1) / TPB;  // 300000 blocks

    // emb0: bufA = concat, acc = emb0, bufB = 0
    lg_init<<<grid_elem, TPB>>>(ue, ie);

    // layer 1: bufB = A @ bufA ; acc += bufB ; bufA = 0
    lg_spmm<<<grid_spmm, TPB>>>(rows, cols, vals, bufA, bufB);
    lg_post<<<grid_elem, TPB>>>(bufB, bufA);

    // layer 2: bufA = A @ bufB ; acc += bufA ; bufB = 0
    lg_spmm<<<grid_spmm, TPB>>>(rows, cols, vals, bufB, bufA);
    lg_post<<<grid_elem, TPB>>>(bufA, bufB);

    // layer 3: bufB = A @ bufA ; out = (acc + bufB) / 4
    lg_spmm<<<grid_spmm, TPB>>>(rows, cols, vals, bufA, bufB);
    lg_final<<<grid_elem, TPB>>>(bufB, out);
}

// round 2
// speedup vs baseline: 1.3501x; 1.3501x over previous
#include <cuda_runtime.h>
#include <cuda_bf16.h>

#define NUM_USERS 100000
#define NUM_ITEMS 50000
#define DIM 64
#define N_TOTAL (NUM_USERS + NUM_ITEMS)
#define NNZ 4800000
#define TOT (N_TOTAL * DIM)   // 9,600,000 floats = 38.4 MB per buffer

// Static scratch: the 4 layer embeddings (e0..e3). 4 x 38.4 MB.
__device__ __align__(16) float g_b0[TOT];
__device__ __align__(16) float g_b1[TOT];
__device__ __align__(16) float g_b2[TOT];
__device__ __align__(16) float g_b3[TOT];

// ---------------------------------------------------------------------------
// init: b0 = concat(user_emb, item_emb); b1 = b2 = b3 = 0
// ---------------------------------------------------------------------------
__global__ void lg_init(const float* __restrict__ ue, const float* __restrict__ ie) {
    const int tot4 = TOT / 4;
    int i = blockIdx.x * blockDim.x + threadIdx.x;
    if (i >= tot4) return;
    const int user4 = (NUM_USERS * DIM) / 4;
    float4 v = (i < user4) ? __ldg((const float4*)ue + i)
                           : __ldg((const float4*)ie + (i - user4));
    float4 z = make_float4(0.f, 0.f, 0.f, 0.f);
    ((float4*)g_b0)[i] = v;
    ((float4*)g_b1)[i] = z;
    ((float4*)g_b2)[i] = z;
    ((float4*)g_b3)[i] = z;
}

// ---------------------------------------------------------------------------
// spmm: y[row] += val * x[col].
// One warp processes 8 edges. Lanes 0..7 load the 8 edges' (row,col,val)
// once (coalesced); each of 4 iterations handles 2 edges with 16 lanes each,
// broadcasting metadata via shfl. Per lane-of-16: one float4 gather + one
// red.global.add.v4.f32 (16B vector reduction, no return).
// ---------------------------------------------------------------------------
__global__ void __launch_bounds__(256) lg_spmm(
        const int* __restrict__ rows, const int* __restrict__ cols,
        const float* __restrict__ vals,
        const float* __restrict__ x, float* __restrict__ y) {
    int gtid = blockIdx.x * blockDim.x + threadIdx.x;
    int warp = gtid >> 5;
    int lane = gtid & 31;
    long base = (long)warp * 8;          // first edge of this warp
    if (base >= NNZ) return;             // NNZ % 8 == 0, so full warps only

    int   r8 = 0, c8 = 0;
    float v8 = 0.f;
    if (lane < 8) {
        r8 = __ldg(rows + base + lane);
        c8 = __ldg(cols + base + lane);
        v8 = __ldg(vals + base + lane);
    }

    int sub = lane >> 4;     // which of the 2 edges in this iteration
    int l16 = lane & 15;     // which float4 of the 64-float row

    #pragma unroll
    for (int i = 0; i < 4; i++) {
        int src = 2 * i + sub;
        int   r = __shfl_sync(0xffffffffu, r8, src);
        int   c = __shfl_sync(0xffffffffu, c8, src);
        float v = __shfl_sync(0xffffffffu, v8, src);

        float4 xv = __ldg((const float4*)(x + (size_t)c * DIM) + l16);
        float px = xv.x * v, py = xv.y * v, pz = xv.z * v, pw = xv.w * v;

        float* dst = y + (size_t)r * DIM + (l16 << 2);
        asm volatile("red.global.add.v4.f32 [%0], {%1, %2, %3, %4};"
                     :: "l"(dst), "f"(px), "f"(py), "f"(pz), "f"(pw)
                     : "memory");
    }
}

// ---------------------------------------------------------------------------
// final: out = 0.25 * (b0 + b1 + b2 + b3)   (mean over the 4 embeddings)
// ---------------------------------------------------------------------------
__global__ void lg_final(float* __restrict__ out) {
    const int tot4 = TOT / 4;
    int i = blockIdx.x * blockDim.x + threadIdx.x;
    if (i >= tot4) return;
    float4 a = ((const float4*)g_b0)[i];
    float4 b = ((const float4*)g_b1)[i];
    float4 c = ((const float4*)g_b2)[i];
    float4 d = ((const float4*)g_b3)[i];
    float4 o = make_float4((a.x + b.x + c.x + d.x) * 0.25f,
                           (a.y + b.y + c.y + d.y) * 0.25f,
                           (a.z + b.z + c.z + d.z) * 0.25f,
                           (a.w + b.w + c.w + d.w) * 0.25f);
    ((float4*)out)[i] = o;
}

extern "C" void kernel_launch(void* const* d_in, const int* in_sizes, int n_in,
                              void* d_out, int out_size) {
    const float* ue   = (const float*)d_in[0];   // user_emb  [100000, 64] f32
    const float* ie   = (const float*)d_in[1];   // item_emb  [50000, 64]  f32
    const float* vals = (const float*)d_in[2];   // adj_vals  [4.8M] f32
    const int*   rows = (const int*)  d_in[3];   // adj_rows  [4.8M] i32
    const int*   cols = (const int*)  d_in[4];   // adj_cols  [4.8M] i32
    float* out = (float*)d_out;

    float *b0, *b1, *b2, *b3;
    cudaGetSymbolAddress((void**)&b0, g_b0);
    cudaGetSymbolAddress((void**)&b1, g_b1);
    cudaGetSymbolAddress((void**)&b2, g_b2);
    cudaGetSymbolAddress((void**)&b3, g_b3);

    const int TPB = 256;
    const int grid_elem = (TOT / 4 + TPB - 1) / TPB;          // 9375 blocks
    // 8 edges per warp, 8 warps per block -> 64 edges per block
    const int grid_spmm = (NNZ + 63) / 64;                    // 75000 blocks

    lg_init<<<grid_elem, TPB>>>(ue, ie);
    lg_spmm<<<grid_spmm, TPB>>>(rows, cols, vals, b0, b1);
    lg_spmm<<<grid_spmm, TPB>>>(rows, cols, vals, b1, b2);
    lg_spmm<<<grid_spmm, TPB>>>(rows, cols, vals, b2, b3);
    lg_final<<<grid_elem, TPB>>>(out);
}

// round 4
// speedup vs baseline: 1.4523x; 1.0757x over previous
#include <cuda_runtime.h>
#include <cuda_bf16.h>

#define NUM_USERS 100000
#define NUM_ITEMS 50000
#define DIM 64
#define N_TOTAL (NUM_USERS + NUM_ITEMS)
#define NNZ 4800000
#define TOT (N_TOTAL * DIM)   // 9,600,000 floats = 38.4 MB per buffer

// Layer embeddings e0..e3
__device__ __align__(16) float g_b0[TOT];
__device__ __align__(16) float g_b1[TOT];
__device__ __align__(16) float g_b2[TOT];
__device__ __align__(16) float g_b3[TOT];

// CSR build scratch
__device__ int g_cnt[N_TOTAL];          // per-row histogram
__device__ int g_rowptr[N_TOTAL + 1];   // exclusive scan
__device__ int g_ofs[N_TOTAL];          // scatter cursors
__device__ __align__(8) int2 g_cv[NNZ]; // CSR pairs: .x = col, .y = val bits

// ---------------------------------------------------------------------------
// init: b0 = concat(user_emb, item_emb); also zero the histogram.
// ---------------------------------------------------------------------------
__global__ void lg_init(const float* __restrict__ ue, const float* __restrict__ ie) {
    const int tot4 = TOT / 4;
    int i = blockIdx.x * blockDim.x + threadIdx.x;
    if (i < N_TOTAL) g_cnt[i] = 0;
    if (i >= tot4) return;
    const int user4 = (NUM_USERS * DIM) / 4;
    float4 v = (i < user4) ? __ldg((const float4*)ue + i)
                           : __ldg((const float4*)ie + (i - user4));
    ((float4*)g_b0)[i] = v;
}

// ---------------------------------------------------------------------------
// histogram of row indices
// ---------------------------------------------------------------------------
__global__ void lg_hist(const int* __restrict__ rows) {
    int e = blockIdx.x * blockDim.x + threadIdx.x;
    if (e >= NNZ) return;
    atomicAdd(&g_cnt[__ldg(rows + e)], 1);
}

// ---------------------------------------------------------------------------
// exclusive scan of g_cnt -> g_rowptr, g_ofs. Single block, 1024 threads,
// sequential chunks with a running carry. 150K elems -> ~147 chunks.
// ---------------------------------------------------------------------------
__global__ void lg_scan() {
    __shared__ int s[1024];
    __shared__ int carry;
    if (threadIdx.x == 0) carry = 0;
    __syncthreads();
    for (int base = 0; base < N_TOTAL; base += 1024) {
        int i = base + threadIdx.x;
        int v = (i < N_TOTAL) ? g_cnt[i] : 0;
        s[threadIdx.x] = v;
        __syncthreads();
        // Hillis-Steele inclusive scan
        #pragma unroll
        for (int d = 1; d < 1024; d <<= 1) {
            int t = (threadIdx.x >= d) ? s[threadIdx.x - d] : 0;
            __syncthreads();
            s[threadIdx.x] += t;
            __syncthreads();
        }
        int excl = s[threadIdx.x] - v + carry;
        if (i < N_TOTAL) { g_rowptr[i] = excl; g_ofs[i] = excl; }
        __syncthreads();
        if (threadIdx.x == 0) carry += s[1023];
        __syncthreads();
    }
    if (threadIdx.x == 0) g_rowptr[N_TOTAL] = NNZ;
}

// ---------------------------------------------------------------------------
// scatter edges into CSR order (order within a row is arbitrary; fp32 sum
// tolerance covers the reassociation).
// ---------------------------------------------------------------------------
__global__ void lg_scatter(const int* __restrict__ rows, const int* __restrict__ cols,
                           const float* __restrict__ vals) {
    int e = blockIdx.x * blockDim.x + threadIdx.x;
    if (e >= NNZ) return;
    int r = __ldg(rows + e);
    int pos = atomicAdd(&g_ofs[r], 1);
    int2 ed;
    ed.x = __ldg(cols + e);
    ed.y = __float_as_int(__ldg(vals + e));
    g_cv[pos] = ed;
}

// ---------------------------------------------------------------------------
// CSR SpMM, gather style, NO atomics. One warp per row; lane l owns output
// floats [2l, 2l+1]. Metadata loaded in 32-edge chunks and shfl-broadcast.
// Per edge: one coalesced LDG.64 of x[c] (256B across the warp) + 2 FMA.
// ---------------------------------------------------------------------------
__global__ void __launch_bounds__(256) lg_csr_spmm(const float* __restrict__ x,
                                                   float* __restrict__ y) {
    int gtid = blockIdx.x * blockDim.x + threadIdx.x;
    int row  = gtid >> 5;
    int lane = gtid & 31;
    if (row >= N_TOTAL) return;

    int beg = __ldg(g_rowptr + row);
    int end = __ldg(g_rowptr + row + 1);

    float ax = 0.f, ay = 0.f;
    for (int j = beg; j < end; j += 32) {
        int jj = j + lane;
        int   c = 0;
        float v = 0.f;
        if (jj < end) {
            int2 ed = __ldg(g_cv + jj);
            c = ed.x; v = __int_as_float(ed.y);
        }
        int m = min(32, end - j);
        for (int k = 0; k < m; k++) {
            int   cc = __shfl_sync(0xffffffffu, c, k);
            float vv = __shfl_sync(0xffffffffu, v, k);
            float2 xv = __ldg((const float2*)(x + (size_t)cc * DIM) + lane);
            ax = fmaf(vv, xv.x, ax);
            ay = fmaf(vv, xv.y, ay);
        }
    }
    float2 o = make_float2(ax, ay);
    ((float2*)(y + (size_t)row * DIM))[lane] = o;
}

// ---------------------------------------------------------------------------
// final: out = 0.25 * (b0 + b1 + b2 + b3)
// ---------------------------------------------------------------------------
__global__ void lg_final(float* __restrict__ out) {
    const int tot4 = TOT / 4;
    int i = blockIdx.x * blockDim.x + threadIdx.x;
    if (i >= tot4) return;
    float4 a = ((const float4*)g_b0)[i];
    float4 b = ((const float4*)g_b1)[i];
    float4 c = ((const float4*)g_b2)[i];
    float4 d = ((const float4*)g_b3)[i];
    float4 o = make_float4((a.x + b.x + c.x + d.x) * 0.25f,
                           (a.y + b.y + c.y + d.y) * 0.25f,
                           (a.z + b.z + c.z + d.z) * 0.25f,
                           (a.w + b.w + c.w + d.w) * 0.25f);
    ((float4*)out)[i] = o;
}

extern "C" void kernel_launch(void* const* d_in, const int* in_sizes, int n_in,
                              void* d_out, int out_size) {
    const float* ue   = (const float*)d_in[0];   // user_emb  [100000, 64] f32
    const float* ie   = (const float*)d_in[1];   // item_emb  [50000, 64]  f32
    const float* vals = (const float*)d_in[2];   // adj_vals  [4.8M] f32
    const int*   rows = (const int*)  d_in[3];   // adj_rows  [4.8M] i32
    const int*   cols = (const int*)  d_in[4];   // adj_cols  [4.8M] i32
    float* out = (float*)d_out;

    float *b0, *b1, *b2, *b3;
    cudaGetSymbolAddress((void**)&b0, g_b0);
    cudaGetSymbolAddress((void**)&b1, g_b1);
    cudaGetSymbolAddress((void**)&b2, g_b2);
    cudaGetSymbolAddress((void**)&b3, g_b3);

    const int TPB = 256;
    const int grid_elem = (TOT / 4 + TPB - 1) / TPB;      // 9375
    const int grid_edge = (NNZ + TPB - 1) / TPB;          // 18750
    const int grid_rows = (N_TOTAL * 32 + TPB - 1) / TPB; // 18750 (warp/row)

    // CSR build (amortized over 3 layers)
    lg_init   <<<grid_elem, TPB>>>(ue, ie);
    lg_hist   <<<grid_edge, TPB>>>(rows);
    lg_scan   <<<1, 1024>>>();
    lg_scatter<<<grid_edge, TPB>>>(rows, cols, vals);

    // 3 gather SpMM layers, no atomics
    lg_csr_spmm<<<grid_rows, TPB>>>(b0, b1);
    lg_csr_spmm<<<grid_rows, TPB>>>(b1, b2);
    lg_csr_spmm<<<grid_rows, TPB>>>(b2, b3);

    lg_final<<<grid_elem, TPB>>>(out);
}

// round 5
// speedup vs baseline: 2.0924x; 1.4408x over previous
#include <cuda_runtime.h>
#include <cuda_bf16.h>

#define NUM_USERS 100000
#define NUM_ITEMS 50000
#define DIM 64
#define N_TOTAL (NUM_USERS + NUM_ITEMS)
#define NNZ 4800000
#define TOT (N_TOTAL * DIM)

#define SCAN_CHUNK 1024
#define NCHUNK ((N_TOTAL + SCAN_CHUNK - 1) / SCAN_CHUNK)   // 147

// Layer embeddings e0..e2 (layer 3 fused into output)
__device__ __align__(16) float g_b0[TOT];
__device__ __align__(16) float g_b1[TOT];
__device__ __align__(16) float g_b2[TOT];

// CSR build scratch
__device__ int g_cnt[N_TOTAL];
__device__ int g_rowptr[N_TOTAL + 1];
__device__ int g_ofs[N_TOTAL];
__device__ int g_bsum[NCHUNK];
__device__ int g_boff[NCHUNK];
__device__ __align__(8) int2 g_cv[NNZ];   // .x = col, .y = val bits

// ---------------------------------------------------------------------------
__global__ void lg_init(const float* __restrict__ ue, const float* __restrict__ ie) {
    const int tot4 = TOT / 4;
    int i = blockIdx.x * blockDim.x + threadIdx.x;
    if (i < N_TOTAL) g_cnt[i] = 0;
    if (i >= tot4) return;
    const int user4 = (NUM_USERS * DIM) / 4;
    float4 v = (i < user4) ? __ldg((const float4*)ue + i)
                           : __ldg((const float4*)ie + (i - user4));
    ((float4*)g_b0)[i] = v;
}

// ---------------------------------------------------------------------------
__global__ void lg_hist(const int* __restrict__ rows) {
    int e = blockIdx.x * blockDim.x + threadIdx.x;
    if (e >= NNZ) return;
    atomicAdd(&g_cnt[__ldg(rows + e)], 1);
}

// ---------------------------------------------------------------------------
// scan phase 1: per-chunk sums (147 blocks x 1024 threads)
// ---------------------------------------------------------------------------
__global__ void lg_reduce() {
    __shared__ int ws[32];
    int tid = threadIdx.x, lane = tid & 31, w = tid >> 5;
    int i = blockIdx.x * SCAN_CHUNK + tid;
    int v = (i < N_TOTAL) ? g_cnt[i] : 0;
    #pragma unroll
    for (int d = 16; d > 0; d >>= 1) v += __shfl_down_sync(0xffffffffu, v, d);
    if (lane == 0) ws[w] = v;
    __syncthreads();
    if (w == 0) {
        int s = ws[lane];
        #pragma unroll
        for (int d = 16; d > 0; d >>= 1) s += __shfl_down_sync(0xffffffffu, s, d);
        if (lane == 0) g_bsum[blockIdx.x] = s;
    }
}

// ---------------------------------------------------------------------------
// scan phase 2: exclusive scan of 147 chunk sums, one block of 256
// ---------------------------------------------------------------------------
__global__ void lg_scanroot() {
    __shared__ int s[256];
    int tid = threadIdx.x;
    int v = (tid < NCHUNK) ? g_bsum[tid] : 0;
    s[tid] = v;
    __syncthreads();
    #pragma unroll
    for (int d = 1; d < 256; d <<= 1) {
        int t = (tid >= d) ? s[tid - d] : 0;
        __syncthreads();
        s[tid] += t;
        __syncthreads();
    }
    if (tid < NCHUNK) g_boff[tid] = s[tid] - v;   // exclusive
}

// ---------------------------------------------------------------------------
// scan phase 3: per-chunk exclusive scan + chunk offset -> rowptr, ofs
// ---------------------------------------------------------------------------
__global__ void lg_scanblk() {
    __shared__ int ws[32];
    int tid = threadIdx.x, lane = tid & 31, w = tid >> 5;
    int i = blockIdx.x * SCAN_CHUNK + tid;
    int v = (i < N_TOTAL) ? g_cnt[i] : 0;
    int inc = v;
    #pragma unroll
    for (int d = 1; d < 32; d <<= 1) {
        int t = __shfl_up_sync(0xffffffffu, inc, d);
        if (lane >= d) inc += t;
    }
    if (lane == 31) ws[w] = inc;
    __syncthreads();
    if (w == 0) {
        int s = ws[lane];
        #pragma unroll
        for (int d = 1; d < 32; d <<= 1) {
            int t = __shfl_up_sync(0xffffffffu, s, d);
            if (lane >= d) s += t;
        }
        ws[lane] = s;
    }
    __syncthreads();
    int excl = inc - v + (w > 0 ? ws[w - 1] : 0) + g_boff[blockIdx.x];
    if (i < N_TOTAL) { g_rowptr[i] = excl; g_ofs[i] = excl; }
    if (blockIdx.x == 0 && tid == 0) g_rowptr[N_TOTAL] = NNZ;
}

// ---------------------------------------------------------------------------
__global__ void lg_scatter(const int* __restrict__ rows, const int* __restrict__ cols,
                           const float* __restrict__ vals) {
    int e = blockIdx.x * blockDim.x + threadIdx.x;
    if (e >= NNZ) return;
    int r = __ldg(rows + e);
    int pos = atomicAdd(&g_ofs[r], 1);
    int2 ed;
    ed.x = __ldg(cols + e);
    ed.y = __float_as_int(__ldg(vals + e));
    g_cv[pos] = ed;
}

// ---------------------------------------------------------------------------
// CSR SpMM core: accumulate row into (ax, ay) for this lane (floats 2l,2l+1).
// Fast path for full 32-edge chunks: batches of 8 shfl+LDG to raise MLP.
// ---------------------------------------------------------------------------
__device__ __forceinline__ void spmm_row(const float* __restrict__ x,
                                         int beg, int end, int lane,
                                         float& ax, float& ay) {
    for (int j = beg; j < end; j += 32) {
        int jj = j + lane;
        int2 ed = make_int2(0, 0);
        if (jj < end) ed = __ldg(g_cv + jj);
        int m = end - j;
        if (m >= 32) {
            #pragma unroll
            for (int k0 = 0; k0 < 32; k0 += 8) {
                int cc[8]; float vv[8]; float2 xv[8];
                #pragma unroll
                for (int k = 0; k < 8; k++) {
                    cc[k] = __shfl_sync(0xffffffffu, ed.x, k0 + k);
                    vv[k] = __int_as_float(__shfl_sync(0xffffffffu, ed.y, k0 + k));
                }
                #pragma unroll
                for (int k = 0; k < 8; k++)
                    xv[k] = __ldg((const float2*)(x + (size_t)cc[k] * DIM) + lane);
                #pragma unroll
                for (int k = 0; k < 8; k++) {
                    ax = fmaf(vv[k], xv[k].x, ax);
                    ay = fmaf(vv[k], xv[k].y, ay);
                }
            }
        } else {
            for (int k = 0; k < m; k++) {
                int   cc = __shfl_sync(0xffffffffu, ed.x, k);
                float vv = __int_as_float(__shfl_sync(0xffffffffu, ed.y, k));
                float2 xv = __ldg((const float2*)(x + (size_t)cc * DIM) + lane);
                ax = fmaf(vv, xv.x, ax);
                ay = fmaf(vv, xv.y, ay);
            }
        }
    }
}

__global__ void __launch_bounds__(256) lg_csr_spmm(const float* __restrict__ x,
                                                   float* __restrict__ y) {
    int gtid = blockIdx.x * blockDim.x + threadIdx.x;
    int row  = gtid >> 5;
    int lane = gtid & 31;
    if (row >= N_TOTAL) return;
    int beg = __ldg(g_rowptr + row);
    int end = __ldg(g_rowptr + row + 1);
    float ax = 0.f, ay = 0.f;
    spmm_row(x, beg, end, lane, ax, ay);
    ((float2*)(y + (size_t)row * DIM))[lane] = make_float2(ax, ay);
}

// Layer 3 fused with the mean: out = 0.25 * (b0 + b1 + b2 + spmm(b2))
__global__ void __launch_bounds__(256) lg_csr_spmm_final(float* __restrict__ out) {
    int gtid = blockIdx.x * blockDim.x + threadIdx.x;
    int row  = gtid >> 5;
    int lane = gtid & 31;
    if (row >= N_TOTAL) return;
    int beg = __ldg(g_rowptr + row);
    int end = __ldg(g_rowptr + row + 1);
    float ax = 0.f, ay = 0.f;
    spmm_row(g_b2, beg, end, lane, ax, ay);
    size_t off = (size_t)row * DIM;
    float2 e0 = ((const float2*)(g_b0 + off))[lane];
    float2 e1 = ((const float2*)(g_b1 + off))[lane];
    float2 e2 = ((const float2*)(g_b2 + off))[lane];
    float2 o = make_float2((e0.x + e1.x + e2.x + ax) * 0.25f,
                           (e0.y + e1.y + e2.y + ay) * 0.25f);
    ((float2*)(out + off))[lane] = o;
}

extern "C" void kernel_launch(void* const* d_in, const int* in_sizes, int n_in,
                              void* d_out, int out_size) {
    const float* ue   = (const float*)d_in[0];
    const float* ie   = (const float*)d_in[1];
    const float* vals = (const float*)d_in[2];
    const int*   rows = (const int*)  d_in[3];
    const int*   cols = (const int*)  d_in[4];
    float* out = (float*)d_out;

    float *b0, *b1, *b2;
    cudaGetSymbolAddress((void**)&b0, g_b0);
    cudaGetSymbolAddress((void**)&b1, g_b1);
    cudaGetSymbolAddress((void**)&b2, g_b2);

    const int TPB = 256;
    const int grid_elem = (TOT / 4 + TPB - 1) / TPB;
    const int grid_edge = (NNZ + TPB - 1) / TPB;
    const int grid_rows = (N_TOTAL * 32 + TPB - 1) / TPB;

    lg_init    <<<grid_elem, TPB>>>(ue, ie);
    lg_hist    <<<grid_edge, TPB>>>(rows);
    lg_reduce  <<<NCHUNK, SCAN_CHUNK>>>();
    lg_scanroot<<<1, 256>>>();
    lg_scanblk <<<NCHUNK, SCAN_CHUNK>>>();
    lg_scatter <<<grid_edge, TPB>>>(rows, cols, vals);

    lg_csr_spmm      <<<grid_rows, TPB>>>(b0, b1);
    lg_csr_spmm      <<<grid_rows, TPB>>>(b1, b2);
    lg_csr_spmm_final<<<grid_rows, TPB>>>(out);
}

// round 6
// speedup vs baseline: 2.1706x; 1.0374x over previous
#include <cuda_runtime.h>
#include <cuda_fp16.h>
#include <cuda_bf16.h>

#define NUM_USERS 100000
#define NUM_ITEMS 50000
#define DIM 64
#define N_TOTAL (NUM_USERS + NUM_ITEMS)
#define NNZ 4800000
#define TOT (N_TOTAL * DIM)

#define SCAN_CHUNK 1024
#define NCHUNK ((N_TOTAL + SCAN_CHUNK - 1) / SCAN_CHUNK)   // 147

// fp32 layer embeddings (for the exact mean epilogue)
__device__ __align__(16) float g_b0[TOT];
__device__ __align__(16) float g_b1[TOT];
__device__ __align__(16) float g_b2[TOT];
// fp16 copies (SpMM gather operands — halves random-gather traffic)
__device__ __align__(16) __half g_h0[TOT];
__device__ __align__(16) __half g_h1[TOT];
__device__ __align__(16) __half g_h2[TOT];

// CSR build scratch
__device__ int g_cnt[N_TOTAL];
__device__ int g_rowptr[N_TOTAL + 1];
__device__ int g_ofs[N_TOTAL];
__device__ int g_bsum[NCHUNK];
__device__ int g_boff[NCHUNK];
__device__ __align__(8) int2 g_cv[NNZ];   // .x = col, .y = val bits (fp32)

// ---------------------------------------------------------------------------
// init: b0 = concat(ue, ie); h0 = fp16(b0); zero histogram.
// ---------------------------------------------------------------------------
__global__ void lg_init(const float* __restrict__ ue, const float* __restrict__ ie) {
    const int tot4 = TOT / 4;
    int i = blockIdx.x * blockDim.x + threadIdx.x;
    if (i < N_TOTAL) g_cnt[i] = 0;
    if (i >= tot4) return;
    const int user4 = (NUM_USERS * DIM) / 4;
    float4 v = (i < user4) ? __ldg((const float4*)ue + i)
                           : __ldg((const float4*)ie + (i - user4));
    ((float4*)g_b0)[i] = v;
    __half2 h01 = __float22half2_rn(make_float2(v.x, v.y));
    __half2 h23 = __float22half2_rn(make_float2(v.z, v.w));
    uint2 packed = make_uint2(*(unsigned*)&h01, *(unsigned*)&h23);
    ((uint2*)g_h0)[i] = packed;
}

// ---------------------------------------------------------------------------
__global__ void lg_hist(const int* __restrict__ rows) {
    int e = blockIdx.x * blockDim.x + threadIdx.x;
    if (e >= NNZ) return;
    atomicAdd(&g_cnt[__ldg(rows + e)], 1);
}

// ---------------------------------------------------------------------------
// scan phase 1: per-chunk sums
// ---------------------------------------------------------------------------
__global__ void lg_reduce() {
    __shared__ int ws[32];
    int tid = threadIdx.x, lane = tid & 31, w = tid >> 5;
    int i = blockIdx.x * SCAN_CHUNK + tid;
    int v = (i < N_TOTAL) ? g_cnt[i] : 0;
    #pragma unroll
    for (int d = 16; d > 0; d >>= 1) v += __shfl_down_sync(0xffffffffu, v, d);
    if (lane == 0) ws[w] = v;
    __syncthreads();
    if (w == 0) {
        int s = ws[lane];
        #pragma unroll
        for (int d = 16; d > 0; d >>= 1) s += __shfl_down_sync(0xffffffffu, s, d);
        if (lane == 0) g_bsum[blockIdx.x] = s;
    }
}

// ---------------------------------------------------------------------------
// scan phase 2: exclusive scan of chunk sums
// ---------------------------------------------------------------------------
__global__ void lg_scanroot() {
    __shared__ int s[256];
    int tid = threadIdx.x;
    int v = (tid < NCHUNK) ? g_bsum[tid] : 0;
    s[tid] = v;
    __syncthreads();
    #pragma unroll
    for (int d = 1; d < 256; d <<= 1) {
        int t = (tid >= d) ? s[tid - d] : 0;
        __syncthreads();
        s[tid] += t;
        __syncthreads();
    }
    if (tid < NCHUNK) g_boff[tid] = s[tid] - v;
}

// ---------------------------------------------------------------------------
// scan phase 3: per-chunk exclusive scan + offset
// ---------------------------------------------------------------------------
__global__ void lg_scanblk() {
    __shared__ int ws[32];
    int tid = threadIdx.x, lane = tid & 31, w = tid >> 5;
    int i = blockIdx.x * SCAN_CHUNK + tid;
    int v = (i < N_TOTAL) ? g_cnt[i] : 0;
    int inc = v;
    #pragma unroll
    for (int d = 1; d < 32; d <<= 1) {
        int t = __shfl_up_sync(0xffffffffu, inc, d);
        if (lane >= d) inc += t;
    }
    if (lane == 31) ws[w] = inc;
    __syncthreads();
    if (w == 0) {
        int s = ws[lane];
        #pragma unroll
        for (int d = 1; d < 32; d <<= 1) {
            int t = __shfl_up_sync(0xffffffffu, s, d);
            if (lane >= d) s += t;
        }
        ws[lane] = s;
    }
    __syncthreads();
    int excl = inc - v + (w > 0 ? ws[w - 1] : 0) + g_boff[blockIdx.x];
    if (i < N_TOTAL) { g_rowptr[i] = excl; g_ofs[i] = excl; }
    if (blockIdx.x == 0 && tid == 0) g_rowptr[N_TOTAL] = NNZ;
}

// ---------------------------------------------------------------------------
__global__ void lg_scatter(const int* __restrict__ rows, const int* __restrict__ cols,
                           const float* __restrict__ vals) {
    int e = blockIdx.x * blockDim.x + threadIdx.x;
    if (e >= NNZ) return;
    int r = __ldg(rows + e);
    int pos = atomicAdd(&g_ofs[r], 1);
    int2 ed;
    ed.x = __ldg(cols + e);
    ed.y = __float_as_int(__ldg(vals + e));
    g_cv[pos] = ed;
}

// ---------------------------------------------------------------------------
// CSR SpMM core: fp16 gather, fp32 accumulate. Lane l owns floats [2l, 2l+1].
// Per edge across the warp: one coalesced 128B gather of xh[c] (half2/lane).
// ---------------------------------------------------------------------------
__device__ __forceinline__ void spmm_row(const __half2* __restrict__ xh,
                                         int beg, int end, int lane,
                                         float& ax, float& ay) {
    for (int j = beg; j < end; j += 32) {
        int jj = j + lane;
        int2 ed = make_int2(0, 0);
        if (jj < end) ed = __ldg(g_cv + jj);
        int m = end - j;
        if (m >= 32) {
            #pragma unroll
            for (int k0 = 0; k0 < 32; k0 += 8) {
                int cc[8]; float vv[8]; __half2 xv[8];
                #pragma unroll
                for (int k = 0; k < 8; k++) {
                    cc[k] = __shfl_sync(0xffffffffu, ed.x, k0 + k);
                    vv[k] = __int_as_float(__shfl_sync(0xffffffffu, ed.y, k0 + k));
                }
                #pragma unroll
                for (int k = 0; k < 8; k++)
                    xv[k] = __ldg(xh + (size_t)cc[k] * 32 + lane);
                #pragma unroll
                for (int k = 0; k < 8; k++) {
                    float2 xf = __half22float2(xv[k]);
                    ax = fmaf(vv[k], xf.x, ax);
                    ay = fmaf(vv[k], xf.y, ay);
                }
            }
        } else {
            for (int k = 0; k < m; k++) {
                int   cc = __shfl_sync(0xffffffffu, ed.x, k);
                float vv = __int_as_float(__shfl_sync(0xffffffffu, ed.y, k));
                float2 xf = __half22float2(__ldg(xh + (size_t)cc * 32 + lane));
                ax = fmaf(vv, xf.x, ax);
                ay = fmaf(vv, xf.y, ay);
            }
        }
    }
}

// y = A @ x (x in fp16); write fp32 y and fp16 yh
__global__ void __launch_bounds__(256) lg_csr_spmm(const __half2* __restrict__ xh,
                                                   float* __restrict__ y,
                                                   __half2* __restrict__ yh) {
    int gtid = blockIdx.x * blockDim.x + threadIdx.x;
    int row  = gtid >> 5;
    int lane = gtid & 31;
    if (row >= N_TOTAL) return;
    int beg = __ldg(g_rowptr + row);
    int end = __ldg(g_rowptr + row + 1);
    float ax = 0.f, ay = 0.f;
    spmm_row(xh, beg, end, lane, ax, ay);
    ((float2*)(y + (size_t)row * DIM))[lane] = make_float2(ax, ay);
    yh[(size_t)row * 32 + lane] = __float22half2_rn(make_float2(ax, ay));
}

// Layer 3 fused with the mean: out = 0.25 * (b0 + b1 + b2 + A@h2)
__global__ void __launch_bounds__(256) lg_csr_spmm_final(float* __restrict__ out) {
    int gtid = blockIdx.x * blockDim.x + threadIdx.x;
    int row  = gtid >> 5;
    int lane = gtid & 31;
    if (row >= N_TOTAL) return;
    int beg = __ldg(g_rowptr + row);
    int end = __ldg(g_rowptr + row + 1);
    float ax = 0.f, ay = 0.f;
    spmm_row((const __half2*)g_h2, beg, end, lane, ax, ay);
    size_t off = (size_t)row * DIM;
    float2 e0 = ((const float2*)(g_b0 + off))[lane];
    float2 e1 = ((const float2*)(g_b1 + off))[lane];
    float2 e2 = ((const float2*)(g_b2 + off))[lane];
    float2 o = make_float2((e0.x + e1.x + e2.x + ax) * 0.25f,
                           (e0.y + e1.y + e2.y + ay) * 0.25f);
    ((float2*)(out + off))[lane] = o;
}

extern "C" void kernel_launch(void* const* d_in, const int* in_sizes, int n_in,
                              void* d_out, int out_size) {
    const float* ue   = (const float*)d_in[0];
    const float* ie   = (const float*)d_in[1];
    const float* vals = (const float*)d_in[2];
    const int*   rows = (const int*)  d_in[3];
    const int*   cols = (const int*)  d_in[4];
    float* out = (float*)d_out;

    float *b1, *b2;
    __half2 *h0, *h1, *h2;
    cudaGetSymbolAddress((void**)&b1, g_b1);
    cudaGetSymbolAddress((void**)&b2, g_b2);
    cudaGetSymbolAddress((void**)&h0, g_h0);
    cudaGetSymbolAddress((void**)&h1, g_h1);
    cudaGetSymbolAddress((void**)&h2, g_h2);

    const int TPB = 256;
    const int grid_elem = (TOT / 4 + TPB - 1) / TPB;
    const int grid_edge = (NNZ + TPB - 1) / TPB;
    const int grid_rows = (N_TOTAL * 32 + TPB - 1) / TPB;

    lg_init    <<<grid_elem, TPB>>>(ue, ie);
    lg_hist    <<<grid_edge, TPB>>>(rows);
    lg_reduce  <<<NCHUNK, SCAN_CHUNK>>>();
    lg_scanroot<<<1, 256>>>();
    lg_scanblk <<<NCHUNK, SCAN_CHUNK>>>();
    lg_scatter <<<grid_edge, TPB>>>(rows, cols, vals);

    lg_csr_spmm      <<<grid_rows, TPB>>>(h0, b1, h1);
    lg_csr_spmm      <<<grid_rows, TPB>>>(h1, b2, h2);
    lg_csr_spmm_final<<<grid_rows, TPB>>>(out);
}

// round 7
// speedup vs baseline: 2.4946x; 1.1492x over previous
#include <cuda_runtime.h>
#include <cuda_fp16.h>
#include <cuda_bf16.h>

#define NUM_USERS 100000
#define NUM_ITEMS 50000
#define DIM 64
#define N_TOTAL (NUM_USERS + NUM_ITEMS)
#define NNZ 4800000
#define TOT (N_TOTAL * DIM)

#define SCAN_CHUNK 1024
#define NCHUNK ((N_TOTAL + SCAN_CHUNK - 1) / SCAN_CHUNK)   // 147

// fp16 layer embeddings (gather operands AND epilogue inputs)
__device__ __align__(16) __half g_h0[TOT];
__device__ __align__(16) __half g_h1[TOT];
__device__ __align__(16) __half g_h2[TOT];

// CSR build scratch
__device__ int g_cnt[N_TOTAL];
__device__ int g_rowptr[N_TOTAL + 1];
__device__ int g_ofs[N_TOTAL];
__device__ int g_bsum[NCHUNK];
__device__ int g_boff[NCHUNK];
__device__ __align__(8) int2 g_cv[NNZ];   // .x = col, .y = val bits (fp32)

// ---------------------------------------------------------------------------
// init: h0 = fp16(concat(ue, ie)); zero histogram.
// ---------------------------------------------------------------------------
__global__ void lg_init(const float* __restrict__ ue, const float* __restrict__ ie) {
    const int tot4 = TOT / 4;
    int i = blockIdx.x * blockDim.x + threadIdx.x;
    if (i < N_TOTAL) g_cnt[i] = 0;
    if (i >= tot4) return;
    const int user4 = (NUM_USERS * DIM) / 4;
    float4 v = (i < user4) ? __ldg((const float4*)ue + i)
                           : __ldg((const float4*)ie + (i - user4));
    __half2 h01 = __float22half2_rn(make_float2(v.x, v.y));
    __half2 h23 = __float22half2_rn(make_float2(v.z, v.w));
    uint2 packed = make_uint2(*(unsigned*)&h01, *(unsigned*)&h23);
    ((uint2*)g_h0)[i] = packed;
}

// ---------------------------------------------------------------------------
__global__ void lg_hist(const int* __restrict__ rows) {
    int e = blockIdx.x * blockDim.x + threadIdx.x;
    if (e >= NNZ) return;
    atomicAdd(&g_cnt[__ldg(rows + e)], 1);
}

// ---------------------------------------------------------------------------
// scan phase 1: per-chunk sums
// ---------------------------------------------------------------------------
__global__ void lg_reduce() {
    __shared__ int ws[32];
    int tid = threadIdx.x, lane = tid & 31, w = tid >> 5;
    int i = blockIdx.x * SCAN_CHUNK + tid;
    int v = (i < N_TOTAL) ? g_cnt[i] : 0;
    #pragma unroll
    for (int d = 16; d > 0; d >>= 1) v += __shfl_down_sync(0xffffffffu, v, d);
    if (lane == 0) ws[w] = v;
    __syncthreads();
    if (w == 0) {
        int s = ws[lane];
        #pragma unroll
        for (int d = 16; d > 0; d >>= 1) s += __shfl_down_sync(0xffffffffu, s, d);
        if (lane == 0) g_bsum[blockIdx.x] = s;
    }
}

// ---------------------------------------------------------------------------
// scan phase 2: exclusive scan of chunk sums
// ---------------------------------------------------------------------------
__global__ void lg_scanroot() {
    __shared__ int s[256];
    int tid = threadIdx.x;
    int v = (tid < NCHUNK) ? g_bsum[tid] : 0;
    s[tid] = v;
    __syncthreads();
    #pragma unroll
    for (int d = 1; d < 256; d <<= 1) {
        int t = (tid >= d) ? s[tid - d] : 0;
        __syncthreads();
        s[tid] += t;
        __syncthreads();
    }
    if (tid < NCHUNK) g_boff[tid] = s[tid] - v;
}

// ---------------------------------------------------------------------------
// scan phase 3: per-chunk exclusive scan + offset
// ---------------------------------------------------------------------------
__global__ void lg_scanblk() {
    __shared__ int ws[32];
    int tid = threadIdx.x, lane = tid & 31, w = tid >> 5;
    int i = blockIdx.x * SCAN_CHUNK + tid;
    int v = (i < N_TOTAL) ? g_cnt[i] : 0;
    int inc = v;
    #pragma unroll
    for (int d = 1; d < 32; d <<= 1) {
        int t = __shfl_up_sync(0xffffffffu, inc, d);
        if (lane >= d) inc += t;
    }
    if (lane == 31) ws[w] = inc;
    __syncthreads();
    if (w == 0) {
        int s = ws[lane];
        #pragma unroll
        for (int d = 1; d < 32; d <<= 1) {
            int t = __shfl_up_sync(0xffffffffu, s, d);
            if (lane >= d) s += t;
        }
        ws[lane] = s;
    }
    __syncthreads();
    int excl = inc - v + (w > 0 ? ws[w - 1] : 0) + g_boff[blockIdx.x];
    if (i < N_TOTAL) { g_rowptr[i] = excl; g_ofs[i] = excl; }
    if (blockIdx.x == 0 && tid == 0) g_rowptr[N_TOTAL] = NNZ;
}

// ---------------------------------------------------------------------------
__global__ void lg_scatter(const int* __restrict__ rows, const int* __restrict__ cols,
                           const float* __restrict__ vals) {
    int e = blockIdx.x * blockDim.x + threadIdx.x;
    if (e >= NNZ) return;
    int r = __ldg(rows + e);
    int pos = atomicAdd(&g_ofs[r], 1);
    int2 ed;
    ed.x = __ldg(cols + e);
    ed.y = __float_as_int(__ldg(vals + e));
    g_cv[pos] = ed;
}

// ---------------------------------------------------------------------------
// CSR SpMM core: fp16 gather, fp32 accumulate. Lane l owns floats [2l, 2l+1].
// ALL edges go through MLP-8 batches; short batches are padded with
// (col=0, val=0) so no serial tail path exists.
// ---------------------------------------------------------------------------
__device__ __forceinline__ void spmm_row(const __half2* __restrict__ xh,
                                         int beg, int end, int lane,
                                         float& ax, float& ay) {
    for (int j = beg; j < end; j += 32) {
        int jj = j + lane;
        int2 ed = (jj < end) ? __ldg(g_cv + jj) : make_int2(0, 0);
        int m = min(32, end - j);
        #pragma unroll
        for (int k0 = 0; k0 < 32; k0 += 8) {
            if (k0 >= m) break;
            int cc[8]; float vv[8]; __half2 xv[8];
            #pragma unroll
            for (int k = 0; k < 8; k++) {
                int src = k0 + k;
                int   c = __shfl_sync(0xffffffffu, ed.x, src);
                float v = __int_as_float(__shfl_sync(0xffffffffu, ed.y, src));
                bool ok = (src < m);
                cc[k] = ok ? c : 0;
                vv[k] = ok ? v : 0.f;
            }
            #pragma unroll
            for (int k = 0; k < 8; k++)
                xv[k] = __ldg(xh + (size_t)cc[k] * 32 + lane);
            #pragma unroll
            for (int k = 0; k < 8; k++) {
                float2 xf = __half22float2(xv[k]);
                ax = fmaf(vv[k], xf.x, ax);
                ay = fmaf(vv[k], xf.y, ay);
            }
        }
    }
}

// yh = fp16(A @ x), x fp16
__global__ void __launch_bounds__(256) lg_csr_spmm(const __half2* __restrict__ xh,
                                                   __half2* __restrict__ yh) {
    int gtid = blockIdx.x * blockDim.x + threadIdx.x;
    int row  = gtid >> 5;
    int lane = gtid & 31;
    if (row >= N_TOTAL) return;
    int beg = __ldg(g_rowptr + row);
    int end = __ldg(g_rowptr + row + 1);
    float ax = 0.f, ay = 0.f;
    spmm_row(xh, beg, end, lane, ax, ay);
    yh[(size_t)row * 32 + lane] = __float22half2_rn(make_float2(ax, ay));
}

// Layer 3 fused with the mean: out = 0.25 * (h0 + h1 + h2 + A@h2)
__global__ void __launch_bounds__(256) lg_csr_spmm_final(float* __restrict__ out) {
    int gtid = blockIdx.x * blockDim.x + threadIdx.x;
    int row  = gtid >> 5;
    int lane = gtid & 31;
    if (row >= N_TOTAL) return;
    int beg = __ldg(g_rowptr + row);
    int end = __ldg(g_rowptr + row + 1);
    float ax = 0.f, ay = 0.f;
    spmm_row((const __half2*)g_h2, beg, end, lane, ax, ay);
    size_t p = (size_t)row * 32 + lane;
    float2 e0 = __half22float2(((const __half2*)g_h0)[p]);
    float2 e1 = __half22float2(((const __half2*)g_h1)[p]);
    float2 e2 = __half22float2(((const __half2*)g_h2)[p]);
    float2 o = make_float2((e0.x + e1.x + e2.x + ax) * 0.25f,
                           (e0.y + e1.y + e2.y + ay) * 0.25f);
    ((float2*)(out + (size_t)row * DIM))[lane] = o;
}

extern "C" void kernel_launch(void* const* d_in, const int* in_sizes, int n_in,
                              void* d_out, int out_size) {
    const float* ue   = (const float*)d_in[0];
    const float* ie   = (const float*)d_in[1];
    const float* vals = (const float*)d_in[2];
    const int*   rows = (const int*)  d_in[3];
    const int*   cols = (const int*)  d_in[4];
    float* out = (float*)d_out;

    __half2 *h0, *h1, *h2;
    cudaGetSymbolAddress((void**)&h0, g_h0);
    cudaGetSymbolAddress((void**)&h1, g_h1);
    cudaGetSymbolAddress((void**)&h2, g_h2);

    const int TPB = 256;
    const int grid_elem = (TOT / 4 + TPB - 1) / TPB;
    const int grid_edge = (NNZ + TPB - 1) / TPB;
    const int grid_rows = (N_TOTAL * 32 + TPB - 1) / TPB;

    lg_init    <<<grid_elem, TPB>>>(ue, ie);
    lg_hist    <<<grid_edge, TPB>>>(rows);
    lg_reduce  <<<NCHUNK, SCAN_CHUNK>>>();
    lg_scanroot<<<1, 256>>>();
    lg_scanblk <<<NCHUNK, SCAN_CHUNK>>>();
    lg_scatter <<<grid_edge, TPB>>>(rows, cols, vals);

    lg_csr_spmm      <<<grid_rows, TPB>>>(h0, h1);
    lg_csr_spmm      <<<grid_rows, TPB>>>(h1, h2);
    lg_csr_spmm_final<<<grid_rows, TPB>>>(out);
}

// round 8
// speedup vs baseline: 2.5739x; 1.0318x over previous
#include <cuda_runtime.h>
#include <cuda_fp16.h>
#include <cuda_bf16.h>

#define NUM_USERS 100000
#define NUM_ITEMS 50000
#define DIM 64
#define N_TOTAL (NUM_USERS + NUM_ITEMS)
#define NNZ 4800000
#define TOT (N_TOTAL * DIM)

#define SCAN_CHUNK 1024
#define NCHUNK ((N_TOTAL + SCAN_CHUNK - 1) / SCAN_CHUNK)   // 147

// fp16 layer embeddings (gather operands AND epilogue inputs)
__device__ __align__(16) __half g_h0[TOT];
__device__ __align__(16) __half g_h1[TOT];
__device__ __align__(16) __half g_h2[TOT];

// CSR build scratch
__device__ int g_cnt[N_TOTAL];
__device__ int g_rowptr[N_TOTAL + 1];
__device__ int g_ofs[N_TOTAL];
__device__ int g_bsum[NCHUNK];
__device__ int g_boff[NCHUNK];
__device__ __align__(8) int2 g_cv[NNZ];   // .x = col, .y = val bits (fp32)

// ---------------------------------------------------------------------------
__global__ void lg_init(const float* __restrict__ ue, const float* __restrict__ ie) {
    const int tot4 = TOT / 4;
    int i = blockIdx.x * blockDim.x + threadIdx.x;
    if (i < N_TOTAL) g_cnt[i] = 0;
    if (i >= tot4) return;
    const int user4 = (NUM_USERS * DIM) / 4;
    float4 v = (i < user4) ? __ldg((const float4*)ue + i)
                           : __ldg((const float4*)ie + (i - user4));
    __half2 h01 = __float22half2_rn(make_float2(v.x, v.y));
    __half2 h23 = __float22half2_rn(make_float2(v.z, v.w));
    uint2 packed = make_uint2(*(unsigned*)&h01, *(unsigned*)&h23);
    ((uint2*)g_h0)[i] = packed;
}

// ---------------------------------------------------------------------------
__global__ void lg_hist(const int* __restrict__ rows) {
    int e = blockIdx.x * blockDim.x + threadIdx.x;
    if (e >= NNZ) return;
    atomicAdd(&g_cnt[__ldcs(rows + e)], 1);
}

// ---------------------------------------------------------------------------
// scan phase 1: per-chunk sums
// ---------------------------------------------------------------------------
__global__ void lg_reduce() {
    __shared__ int ws[32];
    int tid = threadIdx.x, lane = tid & 31, w = tid >> 5;
    int i = blockIdx.x * SCAN_CHUNK + tid;
    int v = (i < N_TOTAL) ? g_cnt[i] : 0;
    #pragma unroll
    for (int d = 16; d > 0; d >>= 1) v += __shfl_down_sync(0xffffffffu, v, d);
    if (lane == 0) ws[w] = v;
    __syncthreads();
    if (w == 0) {
        int s = ws[lane];
        #pragma unroll
        for (int d = 16; d > 0; d >>= 1) s += __shfl_down_sync(0xffffffffu, s, d);
        if (lane == 0) g_bsum[blockIdx.x] = s;
    }
}

// ---------------------------------------------------------------------------
// scan phase 2: exclusive scan of NCHUNK (=147) chunk sums. 256 threads:
// warp-level shfl scan + cross-warp offsets in smem.
// ---------------------------------------------------------------------------
__global__ void lg_scanroot() {
    __shared__ int ws[8];
    int tid = threadIdx.x, lane = tid & 31, w = tid >> 5;
    int v = (tid < NCHUNK) ? g_bsum[tid] : 0;
    int inc = v;
    #pragma unroll
    for (int d = 1; d < 32; d <<= 1) {
        int t = __shfl_up_sync(0xffffffffu, inc, d);
        if (lane >= d) inc += t;
    }
    if (lane == 31) ws[w] = inc;
    __syncthreads();
    if (w == 0 && lane < 8) {
        int s = ws[lane];
        #pragma unroll
        for (int d = 1; d < 8; d <<= 1) {
            int t = __shfl_up_sync(0xffu, s, d);
            if (lane >= d) s += t;
        }
        ws[lane] = s;
    }
    __syncthreads();
    int excl = inc - v + (w > 0 ? ws[w - 1] : 0);
    if (tid < NCHUNK) g_boff[tid] = excl;
}

// ---------------------------------------------------------------------------
// scan phase 3: per-chunk exclusive scan + offset
// ---------------------------------------------------------------------------
__global__ void lg_scanblk() {
    __shared__ int ws[32];
    int tid = threadIdx.x, lane = tid & 31, w = tid >> 5;
    int i = blockIdx.x * SCAN_CHUNK + tid;
    int v = (i < N_TOTAL) ? g_cnt[i] : 0;
    int inc = v;
    #pragma unroll
    for (int d = 1; d < 32; d <<= 1) {
        int t = __shfl_up_sync(0xffffffffu, inc, d);
        if (lane >= d) inc += t;
    }
    if (lane == 31) ws[w] = inc;
    __syncthreads();
    if (w == 0) {
        int s = ws[lane];
        #pragma unroll
        for (int d = 1; d < 32; d <<= 1) {
            int t = __shfl_up_sync(0xffffffffu, s, d);
            if (lane >= d) s += t;
        }
        ws[lane] = s;
    }
    __syncthreads();
    int excl = inc - v + (w > 0 ? ws[w - 1] : 0) + g_boff[blockIdx.x];
    if (i < N_TOTAL) { g_rowptr[i] = excl; g_ofs[i] = excl; }
    if (blockIdx.x == 0 && tid == 0) g_rowptr[N_TOTAL] = NNZ;
}

// ---------------------------------------------------------------------------
__global__ void lg_scatter(const int* __restrict__ rows, const int* __restrict__ cols,
                           const float* __restrict__ vals) {
    int e = blockIdx.x * blockDim.x + threadIdx.x;
    if (e >= NNZ) return;
    int r = __ldcs(rows + e);
    int pos = atomicAdd(&g_ofs[r], 1);
    int2 ed;
    ed.x = __ldcs(cols + e);
    ed.y = __float_as_int(__ldcs(vals + e));
    __stcs(&g_cv[pos], ed);
}

// ---------------------------------------------------------------------------
// CSR SpMM core: fp16 gather, fp32 accumulate. Lane l owns floats [2l, 2l+1].
// Full 32-edge chunks run a branch-free 4x8-batched body (lets ptxas
// front-batch gathers, MLP>=8); only the final partial chunk has predication.
// cv is streamed with __ldcs to protect L2 residency of the x buffers.
// ---------------------------------------------------------------------------
__device__ __forceinline__ void spmm_batch8(const __half2* __restrict__ xh,
                                            int2 ed, int k0, int lane,
                                            float& ax, float& ay) {
    int cc[8]; float vv[8]; __half2 xv[8];
    #pragma unroll
    for (int k = 0; k < 8; k++) {
        cc[k] = __shfl_sync(0xffffffffu, ed.x, k0 + k);
        vv[k] = __int_as_float(__shfl_sync(0xffffffffu, ed.y, k0 + k));
    }
    #pragma unroll
    for (int k = 0; k < 8; k++)
        xv[k] = __ldg(xh + (size_t)cc[k] * 32 + lane);
    #pragma unroll
    for (int k = 0; k < 8; k++) {
        float2 xf = __half22float2(xv[k]);
        ax = fmaf(vv[k], xf.x, ax);
        ay = fmaf(vv[k], xf.y, ay);
    }
}

__device__ __forceinline__ void spmm_row(const __half2* __restrict__ xh,
                                         int beg, int end, int lane,
                                         float& ax, float& ay) {
    int deg = end - beg;
    int full_end = beg + (deg & ~31);
    // full chunks: no bounds checks anywhere
    for (int j = beg; j < full_end; j += 32) {
        int2 ed = __ldcs(g_cv + j + lane);
        #pragma unroll
        for (int k0 = 0; k0 < 32; k0 += 8)
            spmm_batch8(xh, ed, k0, lane, ax, ay);
    }
    // partial tail chunk: padded batches
    int m = end - full_end;
    if (m > 0) {
        int jj = full_end + lane;
        int2 ed = (jj < end) ? __ldcs(g_cv + jj) : make_int2(0, 0);
        #pragma unroll
        for (int k0 = 0; k0 < 32; k0 += 8) {
            if (k0 >= m) break;
            int cc[8]; float vv[8]; __half2 xv[8];
            #pragma unroll
            for (int k = 0; k < 8; k++) {
                int src = k0 + k;
                int   c = __shfl_sync(0xffffffffu, ed.x, src);
                float v = __int_as_float(__shfl_sync(0xffffffffu, ed.y, src));
                bool ok = (src < m);
                cc[k] = ok ? c : 0;
                vv[k] = ok ? v : 0.f;
            }
            #pragma unroll
            for (int k = 0; k < 8; k++)
                xv[k] = __ldg(xh + (size_t)cc[k] * 32 + lane);
            #pragma unroll
            for (int k = 0; k < 8; k++) {
                float2 xf = __half22float2(xv[k]);
                ax = fmaf(vv[k], xf.x, ax);
                ay = fmaf(vv[k], xf.y, ay);
            }
        }
    }
}

// yh = fp16(A @ x), x fp16
__global__ void __launch_bounds__(256) lg_csr_spmm(const __half2* __restrict__ xh,
                                                   __half2* __restrict__ yh) {
    int gtid = blockIdx.x * blockDim.x + threadIdx.x;
    int row  = gtid >> 5;
    int lane = gtid & 31;
    if (row >= N_TOTAL) return;
    int beg = __ldg(g_rowptr + row);
    int end = __ldg(g_rowptr + row + 1);
    float ax = 0.f, ay = 0.f;
    spmm_row(xh, beg, end, lane, ax, ay);
    yh[(size_t)row * 32 + lane] = __float22half2_rn(make_float2(ax, ay));
}

// Layer 3 fused with the mean: out = 0.25 * (h0 + h1 + h2 + A@h2)
__global__ void __launch_bounds__(256) lg_csr_spmm_final(float* __restrict__ out) {
    int gtid = blockIdx.x * blockDim.x + threadIdx.x;
    int row  = gtid >> 5;
    int lane = gtid & 31;
    if (row >= N_TOTAL) return;
    int beg = __ldg(g_rowptr + row);
    int end = __ldg(g_rowptr + row + 1);
    float ax = 0.f, ay = 0.f;
    spmm_row((const __half2*)g_h2, beg, end, lane, ax, ay);
    size_t p = (size_t)row * 32 + lane;
    float2 e0 = __half22float2(((const __half2*)g_h0)[p]);
    float2 e1 = __half22float2(((const __half2*)g_h1)[p]);
    float2 e2 = __half22float2(((const __half2*)g_h2)[p]);
    float2 o = make_float2((e0.x + e1.x + e2.x + ax) * 0.25f,
                           (e0.y + e1.y + e2.y + ay) * 0.25f);
    ((float2*)(out + (size_t)row * DIM))[lane] = o;
}

extern "C" void kernel_launch(void* const* d_in, const int* in_sizes, int n_in,
                              void* d_out, int out_size) {
    const float* ue   = (const float*)d_in[0];
    const float* ie   = (const float*)d_in[1];
    const float* vals = (const float*)d_in[2];
    const int*   rows = (const int*)  d_in[3];
    const int*   cols = (const int*)  d_in[4];
    float* out = (float*)d_out;

    __half2 *h0, *h1, *h2;
    cudaGetSymbolAddress((void**)&h0, g_h0);
    cudaGetSymbolAddress((void**)&h1, g_h1);
    cudaGetSymbolAddress((void**)&h2, g_h2);

    const int TPB = 256;
    const int grid_elem = (TOT / 4 + TPB - 1) / TPB;
    const int grid_edge = (NNZ + TPB - 1) / TPB;
    const int grid_rows = (N_TOTAL * 32 + TPB - 1) / TPB;

    lg_init    <<<grid_elem, TPB>>>(ue, ie);
    lg_hist    <<<grid_edge, TPB>>>(rows);
    lg_reduce  <<<NCHUNK, SCAN_CHUNK>>>();
    lg_scanroot<<<1, 256>>>();
    lg_scanblk <<<NCHUNK, SCAN_CHUNK>>>();
    lg_scatter <<<grid_edge, TPB>>>(rows, cols, vals);

    lg_csr_spmm      <<<grid_rows, TPB>>>(h0, h1);
    lg_csr_spmm      <<<grid_rows, TPB>>>(h1, h2);
    lg_csr_spmm_final<<<grid_rows, TPB>>>(out);
}